// round 10
// baseline (speedup 1.0000x reference)
#include <cuda_runtime.h>
#include <cuda_bf16.h>
#include <math.h>
#include <stdint.h>

// Batched log(M) for SPD 64x64 matrices, spectrum in [1, 6]:
// degree-8 Chebyshev poly of log in T = (M - 3.5 I)/2.5, PS s=2 (4 matmuls),
// mma.sync m16n8k16 bf16 (HMMA), 2-way truncation split, 3-term products.
// 1 matrix/CTA, 128 threads, IN-PLACE AC updates -> 32KB smem -> 5 CTAs/SM
// (20 warps). Step-0 diagonal warps alias B-frags to A-frags (X=Y=T).

constexpr int DEG = 8;
struct Poly { float a[DEG + 1]; };

constexpr int TILE = 8192;            // one 64x64 bf16 tile
constexpr int SMEM_TOT = 4 * TILE;    // Xh,Xl (T -> AC in place) | T2h,T2l

__device__ __forceinline__ uint32_t smem_u32(const void* p) {
    uint32_t a;
    asm("{ .reg .u64 t; cvta.to.shared.u64 t, %1; cvt.u32.u64 %0, t; }"
        : "=r"(a) : "l"(p));
    return a;
}
__device__ __forceinline__ void sts32(uint32_t addr, uint32_t v) {
    asm volatile("st.shared.b32 [%0], %1;" :: "r"(addr), "r"(v));
}
__device__ __forceinline__ uint32_t lds32(uint32_t addr) {
    uint32_t v;
    asm volatile("ld.shared.b32 %0, [%1];" : "=r"(v) : "r"(addr));
    return v;
}
__device__ __forceinline__ uint32_t packbf(float lo, float hi) {
    uint32_t r;
    asm("cvt.rn.bf16x2.f32 %0, %1, %2;" : "=r"(r) : "f"(hi), "f"(lo));
    return r;
}
__device__ __forceinline__ float2 unpackbf(uint32_t u) {
    const __nv_bfloat162 b = *reinterpret_cast<const __nv_bfloat162*>(&u);
    return make_float2(__bfloat162float(b.x), __bfloat162float(b.y));
}
// truncation split of a pair: h = [x0.hi16|x1.hi16], l = residuals as bf16x2
__device__ __forceinline__ void split_pair(float x0, float x1,
                                           uint32_t& h01, uint32_t& l01) {
    const uint32_t u0 = __float_as_uint(x0), u1 = __float_as_uint(x1);
    asm("prmt.b32 %0, %1, %2, 0x7632;" : "=r"(h01) : "r"(u0), "r"(u1));
    const float l0 = x0 - __uint_as_float(u0 & 0xFFFF0000u);
    const float l1 = x1 - __uint_as_float(u1 & 0xFFFF0000u);
    l01 = packbf(l0, l1);
}
__device__ __forceinline__ void ldsm4(uint32_t r[4], uint32_t addr) {
    asm volatile("ldmatrix.sync.aligned.m8n8.x4.shared.b16 {%0,%1,%2,%3}, [%4];"
                 : "=r"(r[0]), "=r"(r[1]), "=r"(r[2]), "=r"(r[3]) : "r"(addr));
}
__device__ __forceinline__ void mma16816(float c[4], const uint32_t a[4],
                                         uint32_t b0, uint32_t b1) {
    asm volatile(
        "mma.sync.aligned.m16n8k16.row.col.f32.bf16.bf16.f32 "
        "{%0,%1,%2,%3}, {%4,%5,%6,%7}, {%8,%9}, {%0,%1,%2,%3};"
        : "+f"(c[0]), "+f"(c[1]), "+f"(c[2]), "+f"(c[3])
        : "r"(a[0]), "r"(a[1]), "r"(a[2]), "r"(a[3]), "r"(b0), "r"(b1));
}

// 12 MMAs: one nj-group (n16) x 2 mi x (3 split terms)
__device__ __forceinline__ void mma_nj(float acc[8][4], int nj,
                                       const uint32_t ah0[4], const uint32_t al0[4],
                                       const uint32_t ah1[4], const uint32_t al1[4],
                                       const uint32_t bh[4], const uint32_t bl[4]) {
#pragma unroll
    for (int mi = 0; mi < 2; ++mi) {
        const uint32_t* ah = mi ? ah1 : ah0;
        const uint32_t* al = mi ? al1 : al0;
#pragma unroll
        for (int sub = 0; sub < 2; ++sub) {
            float* c = acc[mi * 4 + nj * 2 + sub];
            mma16816(c, ah, bh[sub], bh[sub + 2]);   // Ah*Bh
            mma16816(c, ah, bl[sub], bl[sub + 2]);   // Ah*Bl
            mma16816(c, al, bh[sub], bh[sub + 2]);   // Al*Bh
        }
    }
}

// one full matmul: acc = X * Y^T (X row-major k-contig hi at Xh, lo at +TILE).
// DIAG: Y rows == X rows -> B-frags alias A-frags (skip 8 ldsm4/chunk).
template <bool DIAG>
__device__ __forceinline__ void mm_step(float acc[8][4],
                                        uint32_t Xh, uint32_t Yh,
                                        uint32_t rX, uint32_t rY, uint32_t msk) {
#pragma unroll
    for (int t = 0; t < 8; ++t)
#pragma unroll
        for (int e = 0; e < 4; ++e) acc[t][e] = 0.0f;
#pragma unroll
    for (int ks = 0; ks < 4; ++ks) {
        const uint32_t kb = (uint32_t)(ks * 32);
        const uint32_t xa = Xh + ((rX + kb) ^ msk);
        uint32_t ah0[4], ah1[4], al0[4], al1[4];
        ldsm4(ah0, xa);        ldsm4(ah1, xa + 2048);
        ldsm4(al0, xa + TILE); ldsm4(al1, xa + TILE + 2048);
        if (DIAG) {
            mma_nj(acc, 0, ah0, al0, ah1, al1, ah0, al0);
            mma_nj(acc, 1, ah0, al0, ah1, al1, ah1, al1);
        } else {
            const uint32_t ya = Yh + ((rY + kb) ^ msk);
#pragma unroll
            for (int nj = 0; nj < 2; ++nj) {
                uint32_t bh[4], bl[4];
                ldsm4(bh, ya + nj * 2048);
                ldsm4(bl, ya + TILE + nj * 2048);
                mma_nj(acc, nj, ah0, al0, ah1, al1, bh, bl);
            }
        }
    }
}

__global__ __launch_bounds__(128, 5)
void logm_hmma_kernel(const float* __restrict__ gin,
                      float* __restrict__ gout,
                      Poly P) {
    extern __shared__ char smc[];
    const uint32_t sb  = smem_u32(smc);
    const uint32_t bX  = sb;              // T, then AC (in place)
    const uint32_t bT2 = sb + 2 * TILE;

    const int tid  = threadIdx.x;
    const int warp = tid >> 5;
    const int lane = tid & 31;
    const int row0 = (warp >> 1) * 32;
    const int col0 = (warp & 1) * 32;

    // ---- prologue: T = (M - 3.5 I)/2.5, truncation-split into bX
    {
        const int pr = tid >> 1, ph = tid & 1;
        const float* gp = gin + (size_t)blockIdx.x * 4096 + pr * 64 + ph * 32;
        float v[32];
#pragma unroll
        for (int j = 0; j < 32; j += 4) {
            const float4 t4 = *reinterpret_cast<const float4*>(gp + j);
            v[j] = t4.x; v[j + 1] = t4.y; v[j + 2] = t4.z; v[j + 3] = t4.w;
        }
        const float inv_beta = 1.0f / 2.5f, alpha = 3.5f;
#pragma unroll
        for (int j = 0; j < 32; ++j)
            v[j] = (v[j] - ((ph * 32 + j == pr) ? alpha : 0.0f)) * inv_beta;

        const uint32_t pmsk = (uint32_t)((pr & 7) << 4);
#pragma unroll
        for (int j = 0; j < 16; ++j) {
            const uint32_t off = ((uint32_t)(pr * 128 + ph * 64 + 4 * j)) ^ pmsk;
            uint32_t h01, l01;
            split_pair(v[2 * j], v[2 * j + 1], h01, l01);
            sts32(bX + off, h01);
            sts32(bX + TILE + off, l01);
        }
    }
    __syncthreads();

    // ---- per-thread constant geometry
    const int la = lane & 15, lc = lane >> 4;
    const uint32_t msk = (uint32_t)((la & 7) << 4);
    const uint32_t rX  = (uint32_t)((row0 + la) * 128 + lc * 16);
    const uint32_t rY  = (uint32_t)((col0 + la) * 128 + lc * 16);
    const int er = lane >> 2, ec = (lane & 3) * 2;
    const uint32_t mskE = (uint32_t)((er & 7) << 4);
    const uint32_t rE0  = (uint32_t)((row0 + er) * 128 + (col0 + ec) * 2);
    const bool diag = (row0 == col0);

    // T fragments hoisted (bX gets overwritten by AC); diag masks
    float2   Treg[16];
    uint32_t dm0 = 0, dm1 = 0;
#pragma unroll
    for (int mi = 0; mi < 2; ++mi)
#pragma unroll
        for (int ni = 0; ni < 4; ++ni)
#pragma unroll
            for (int hf = 0; hf < 2; ++hf) {
                const int pos = mi * 8 + ni * 2 + hf;
                const uint32_t rel =
                    (rE0 + (uint32_t)(mi * 2048 + ni * 16 + hf * 1024)) ^ mskE;
                const float2 th = unpackbf(lds32(bX + rel));
                const float2 tl = unpackbf(lds32(bX + TILE + rel));
                Treg[pos] = make_float2(th.x + tl.x, th.y + tl.y);
                const int gr = row0 + mi * 16 + er + hf * 8;
                const int gc = col0 + ni * 8 + ec;
                if (gr == gc)     dm0 |= 1u << pos;
                if (gr == gc + 1) dm1 |= 1u << pos;
            }

    float acc[8][4];

#pragma unroll
    for (int step = 0; step < 4; ++step) {
        // mm: step0 X=Y=T (diag warps alias); steps>=1 X=AC, Y=T2
        if (step == 0 && diag) mm_step<true >(acc, bX, bX,  rX, rY, msk);
        else if (step == 0)    mm_step<false>(acc, bX, bX,  rX, rY, msk);
        else                   mm_step<false>(acc, bX, bT2, rX, rY, msk);

        float cd, c1, cc0;
        if      (step == 0) { cd = P.a[8]; c1 = P.a[7]; cc0 = P.a[6]; }
        else if (step == 1) { cd = 1.0f;   c1 = P.a[5]; cc0 = P.a[4]; }
        else if (step == 2) { cd = 1.0f;   c1 = P.a[3]; cc0 = P.a[2]; }
        else                { cd = 1.0f;   c1 = P.a[1]; cc0 = P.a[0]; }

        if (step < 3) __syncthreads();   // all X reads done -> safe to overwrite

#pragma unroll
        for (int mi = 0; mi < 2; ++mi)
#pragma unroll
            for (int ni = 0; ni < 4; ++ni)
#pragma unroll
                for (int hf = 0; hf < 2; ++hf) {
                    const int pos = mi * 8 + ni * 2 + hf;
                    const float d0 = acc[mi * 4 + ni][2 * hf];
                    const float d1 = acc[mi * 4 + ni][2 * hf + 1];
                    float x0 = cd * d0 + c1 * Treg[pos].x;
                    float x1 = cd * d1 + c1 * Treg[pos].y;
                    if ((dm0 >> pos) & 1) x0 += cc0;
                    if ((dm1 >> pos) & 1) x1 += cc0;
                    if (step < 3) {
                        const uint32_t rel =
                            (rE0 + (uint32_t)(mi * 2048 + ni * 16 + hf * 1024)) ^ mskE;
                        if (step == 0) {            // raw acc IS T2
                            uint32_t t2h, t2l;
                            split_pair(d0, d1, t2h, t2l);
                            sts32(bT2 + rel, t2h);
                            sts32(bT2 + TILE + rel, t2l);
                        }
                        uint32_t h01, l01;
                        split_pair(x0, x1, h01, l01);
                        sts32(bX + rel, h01);       // in-place AC
                        sts32(bX + TILE + rel, l01);
                    } else {
                        const int gr = row0 + mi * 16 + er + hf * 8;
                        const int gc = col0 + ni * 8 + ec;
                        float2* gp = reinterpret_cast<float2*>(
                            gout + (size_t)blockIdx.x * 4096 + gr * 64 + gc);
                        *gp = make_float2(x0, x1);
                    }
                }
        if (step < 3) __syncthreads();   // writes visible before next mm
    }
}

extern "C" void kernel_launch(void* const* d_in, const int* in_sizes, int n_in,
                              void* d_out, int out_size) {
    const float* in = (const float*)d_in[0];
    float* out = (float*)d_out;
    const int nmat = in_sizes[0] / 4096;   // 8192 matrices of 64x64

    // Chebyshev coefficients of log on [1,6], converted to monomial basis.
    Poly P;
    {
        const double alpha = 3.5, beta = 2.5;
        const double r = (alpha - sqrt(alpha * alpha - beta * beta)) / beta;
        double c[DEG + 1];
        c[0] = log(alpha / (1.0 + r * r));
        double rk = 1.0;
        for (int k = 1; k <= DEG; ++k) {
            rk *= r;
            c[k] = ((k & 1) ? 2.0 : -2.0) * rk / (double)k;
        }
        double mono[DEG + 1], Tm1[DEG + 1], Tc[DEG + 1], Tn[DEG + 1];
        for (int j = 0; j <= DEG; ++j) { mono[j] = 0; Tm1[j] = 0; Tc[j] = 0; }
        Tm1[0] = 1.0;            // T0
        Tc[1]  = 1.0;            // T1
        for (int j = 0; j <= DEG; ++j) mono[j] = c[0] * Tm1[j] + c[1] * Tc[j];
        for (int k = 2; k <= DEG; ++k) {
            for (int j = 0; j <= DEG; ++j) {
                double t = -Tm1[j];
                if (j > 0) t += 2.0 * Tc[j - 1];
                Tn[j] = t;
            }
            for (int j = 0; j <= DEG; ++j) {
                mono[j] += c[k] * Tn[j];
                Tm1[j] = Tc[j];
                Tc[j]  = Tn[j];
            }
        }
        for (int j = 0; j <= DEG; ++j) P.a[j] = (float)mono[j];
    }

    cudaFuncSetAttribute(logm_hmma_kernel,
                         cudaFuncAttributeMaxDynamicSharedMemorySize, SMEM_TOT);
    logm_hmma_kernel<<<nmat, 128, SMEM_TOT>>>(in, out, P);
}

// round 11
// speedup vs baseline: 1.5772x; 1.5772x over previous
#include <cuda_runtime.h>
#include <cuda_bf16.h>
#include <math.h>
#include <stdint.h>

// Batched log(M) for SPD 64x64 matrices, spectrum in [1, 6]:
// degree-8 Chebyshev poly of log in T = (M - 3.5 I)/2.5, PS s=2 (4 matmuls),
// mma.sync m16n8k16 bf16 (HMMA), 2-way truncation split, 3-term products.
// Row-block decomposition: each warp owns 16 rows x 64 cols of C, so the
// next step's A-fragments come straight from its own accumulators (C-frag
// layout == A-frag layout). AC never touches smem; only T (step 0) and the
// exactly-symmetric T2 (steps 1-3, read-only) live in smem. One barrier
// after step 0; steps 1-3 run barrier-free. 32KB smem/CTA.

constexpr int DEG = 8;
struct Poly { float a[DEG + 1]; };

constexpr int TILE = 8192;            // one 64x64 bf16 tile
constexpr int SMEM_TOT = 4 * TILE;    // Th,Tl | T2h,T2l

__device__ __forceinline__ uint32_t smem_u32(const void* p) {
    uint32_t a;
    asm("{ .reg .u64 t; cvta.to.shared.u64 t, %1; cvt.u32.u64 %0, t; }"
        : "=r"(a) : "l"(p));
    return a;
}
__device__ __forceinline__ void sts32(uint32_t addr, uint32_t v) {
    asm volatile("st.shared.b32 [%0], %1;" :: "r"(addr), "r"(v));
}
__device__ __forceinline__ uint32_t lds32(uint32_t addr) {
    uint32_t v;
    asm volatile("ld.shared.b32 %0, [%1];" : "=r"(v) : "r"(addr));
    return v;
}
__device__ __forceinline__ uint32_t packbf(float lo, float hi) {
    uint32_t r;
    asm("cvt.rn.bf16x2.f32 %0, %1, %2;" : "=r"(r) : "f"(hi), "f"(lo));
    return r;
}
__device__ __forceinline__ float2 unpackbf(uint32_t u) {
    const __nv_bfloat162 b = *reinterpret_cast<const __nv_bfloat162*>(&u);
    return make_float2(__bfloat162float(b.x), __bfloat162float(b.y));
}
// truncation split of a pair: h = [x0.hi16|x1.hi16] (x0 in low half),
// l = residuals as bf16x2
__device__ __forceinline__ void split_pair(float x0, float x1,
                                           uint32_t& h01, uint32_t& l01) {
    const uint32_t u0 = __float_as_uint(x0), u1 = __float_as_uint(x1);
    asm("prmt.b32 %0, %1, %2, 0x7632;" : "=r"(h01) : "r"(u0), "r"(u1));
    const float l0 = x0 - __uint_as_float(u0 & 0xFFFF0000u);
    const float l1 = x1 - __uint_as_float(u1 & 0xFFFF0000u);
    l01 = packbf(l0, l1);
}
__device__ __forceinline__ void ldsm4(uint32_t r[4], uint32_t addr) {
    asm volatile("ldmatrix.sync.aligned.m8n8.x4.shared.b16 {%0,%1,%2,%3}, [%4];"
                 : "=r"(r[0]), "=r"(r[1]), "=r"(r[2]), "=r"(r[3]) : "r"(addr));
}
__device__ __forceinline__ void mma16816(float c[4], const uint32_t a[4],
                                         uint32_t b0, uint32_t b1) {
    asm volatile(
        "mma.sync.aligned.m16n8k16.row.col.f32.bf16.bf16.f32 "
        "{%0,%1,%2,%3}, {%4,%5,%6,%7}, {%8,%9}, {%0,%1,%2,%3};"
        : "+f"(c[0]), "+f"(c[1]), "+f"(c[2]), "+f"(c[3])
        : "r"(a[0]), "r"(a[1]), "r"(a[2]), "r"(a[3]), "r"(b0), "r"(b1));
}

// One k16 chunk of C(16x64) += A(16x16) * Y^T: loads B-frags for 4 n16
// groups from ybase (pre-swizzled; +nj*2048 preserves the swizzle since the
// row%8 bits don't change) and issues 24 MMAs (3 split terms).
__device__ __forceinline__ void mma_k16(float acc[8][4],
                                        const uint32_t ah[4], const uint32_t al[4],
                                        uint32_t ybase) {
#pragma unroll
    for (int nj = 0; nj < 4; ++nj) {
        uint32_t bh[4], bl[4];
        ldsm4(bh, ybase + nj * 2048);
        ldsm4(bl, ybase + nj * 2048 + TILE);
#pragma unroll
        for (int sub = 0; sub < 2; ++sub) {
            float* c = acc[nj * 2 + sub];
            mma16816(c, ah, bh[sub], bh[sub + 2]);   // Ah*Bh
            mma16816(c, ah, bl[sub], bl[sub + 2]);   // Ah*Bl
            mma16816(c, al, bh[sub], bh[sub + 2]);   // Al*Bh
        }
    }
}

__global__ __launch_bounds__(128, 4)
void logm_hmma_kernel(const float* __restrict__ gin,
                      float* __restrict__ gout,
                      Poly P) {
    extern __shared__ char smc[];
    const uint32_t sb  = smem_u32(smc);
    const uint32_t bT  = sb;              // T hi (+TILE = lo), persistent
    const uint32_t bT2 = sb + 2 * TILE;   // T2 hi (+TILE = lo), written step 0

    const int tid  = threadIdx.x;
    const int warp = tid >> 5;
    const int lane = tid & 31;
    const int row0 = warp * 16;           // warp owns rows [row0, row0+16)

    // ---- prologue: T = (M - 3.5 I)/2.5, truncation-split into bT
    {
        const int pr = tid >> 1, ph = tid & 1;
        const float* gp = gin + (size_t)blockIdx.x * 4096 + pr * 64 + ph * 32;
        float v[32];
#pragma unroll
        for (int j = 0; j < 32; j += 4) {
            const float4 t4 = *reinterpret_cast<const float4*>(gp + j);
            v[j] = t4.x; v[j + 1] = t4.y; v[j + 2] = t4.z; v[j + 3] = t4.w;
        }
        const float inv_beta = 1.0f / 2.5f, alpha = 3.5f;
#pragma unroll
        for (int j = 0; j < 32; ++j)
            v[j] = (v[j] - ((ph * 32 + j == pr) ? alpha : 0.0f)) * inv_beta;

        const uint32_t pmsk = (uint32_t)((pr & 7) << 4);
#pragma unroll
        for (int j = 0; j < 16; ++j) {
            const uint32_t off = ((uint32_t)(pr * 128 + ph * 64 + 4 * j)) ^ pmsk;
            uint32_t h01, l01;
            split_pair(v[2 * j], v[2 * j + 1], h01, l01);
            sts32(bT + off, h01);
            sts32(bT + TILE + off, l01);
        }
    }
    __syncthreads();

    // ---- per-thread constant geometry
    const int la = lane & 15, lc = lane >> 4;
    const uint32_t msk = (uint32_t)((la & 7) << 4);
    const uint32_t rA  = (uint32_t)((row0 + la) * 128 + lc * 16);  // A rows
    const uint32_t rY  = (uint32_t)(la * 128 + lc * 16);           // B rows (nj via +2048)
    const int er = lane >> 2, ec = (lane & 3) * 2;
    const uint32_t mskE = (uint32_t)(er << 4);                     // er in [0,8)
    const uint32_t rE0  = (uint32_t)((row0 + er) * 128 + ec * 2);

    // diag masks over pos = ni*2+hf
    uint32_t dm0 = 0, dm1 = 0;
#pragma unroll
    for (int ni = 0; ni < 8; ++ni)
#pragma unroll
        for (int hf = 0; hf < 2; ++hf) {
            const int gr = row0 + er + hf * 8;
            const int gc = ni * 8 + ec;
            if (gr == gc)     dm0 |= 1u << (ni * 2 + hf);
            if (gr == gc + 1) dm1 |= 1u << (ni * 2 + hf);
        }

    float    acc[8][4];
    uint32_t fh[16], fl[16];   // A-fragments of own AC rows (pos = ni*2+hf)

#pragma unroll
    for (int step = 0; step < 4; ++step) {
#pragma unroll
        for (int t = 0; t < 8; ++t)
#pragma unroll
            for (int e = 0; e < 4; ++e) acc[t][e] = 0.0f;

        // ---- mm: C(own 16 rows) = X * Y^T
#pragma unroll
        for (int ks = 0; ks < 4; ++ks) {
            const uint32_t kb = (uint32_t)(ks * 32);
            if (step == 0) {
                const uint32_t xa = bT + ((rA + kb) ^ msk);
                uint32_t ah[4], al[4];
                ldsm4(ah, xa);
                ldsm4(al, xa + TILE);
                mma_k16(acc, ah, al, bT + ((rY + kb) ^ msk));
            } else {
                // A-frags for chunk ks are fh/fl[4ks..4ks+3] (C-frag layout
                // == A-frag layout: a0..a3 = pos {2ks,0},{2ks,1},{2ks+1,0},{2ks+1,1})
                mma_k16(acc, &fh[4 * ks], &fl[4 * ks], bT2 + ((rY + kb) ^ msk));
            }
        }

        float cd, c1, cc0;
        if      (step == 0) { cd = P.a[8]; c1 = P.a[7]; cc0 = P.a[6]; }
        else if (step == 1) { cd = 1.0f;   c1 = P.a[5]; cc0 = P.a[4]; }
        else if (step == 2) { cd = 1.0f;   c1 = P.a[3]; cc0 = P.a[2]; }
        else                { cd = 1.0f;   c1 = P.a[1]; cc0 = P.a[0]; }

        // ---- epilogue: AC = cd*D + c1*T + cc0*I, kept in registers as
        // next step's A-fragments. T re-read from persistent bT.
#pragma unroll
        for (int ni = 0; ni < 8; ++ni)
#pragma unroll
            for (int hf = 0; hf < 2; ++hf) {
                const int pos = ni * 2 + hf;
                const uint32_t rel =
                    (rE0 + (uint32_t)(ni * 16 + hf * 1024)) ^ mskE;
                const float d0 = acc[ni][2 * hf];
                const float d1 = acc[ni][2 * hf + 1];
                if (step == 0) {               // raw acc IS T2 (exactly symmetric)
                    uint32_t t2h, t2l;
                    split_pair(d0, d1, t2h, t2l);
                    sts32(bT2 + rel, t2h);
                    sts32(bT2 + TILE + rel, t2l);
                }
                const float2 th = unpackbf(lds32(bT + rel));
                const float2 tl = unpackbf(lds32(bT + TILE + rel));
                float x0 = cd * d0 + c1 * (th.x + tl.x);
                float x1 = cd * d1 + c1 * (th.y + tl.y);
                if ((dm0 >> pos) & 1) x0 += cc0;
                if ((dm1 >> pos) & 1) x1 += cc0;
                if (step < 3) {
                    split_pair(x0, x1, fh[pos], fl[pos]);
                } else {
                    const int gr = row0 + er + hf * 8;
                    const int gc = ni * 8 + ec;
                    float2* gp = reinterpret_cast<float2*>(
                        gout + (size_t)blockIdx.x * 4096 + gr * 64 + gc);
                    *gp = make_float2(x0, x1);
                }
            }

        if (step == 0) __syncthreads();   // T2 visible; steps 1-3 barrier-free
    }
}

extern "C" void kernel_launch(void* const* d_in, const int* in_sizes, int n_in,
                              void* d_out, int out_size) {
    const float* in = (const float*)d_in[0];
    float* out = (float*)d_out;
    const int nmat = in_sizes[0] / 4096;   // 8192 matrices of 64x64

    // Chebyshev coefficients of log on [1,6], converted to monomial basis.
    Poly P;
    {
        const double alpha = 3.5, beta = 2.5;
        const double r = (alpha - sqrt(alpha * alpha - beta * beta)) / beta;
        double c[DEG + 1];
        c[0] = log(alpha / (1.0 + r * r));
        double rk = 1.0;
        for (int k = 1; k <= DEG; ++k) {
            rk *= r;
            c[k] = ((k & 1) ? 2.0 : -2.0) * rk / (double)k;
        }
        double mono[DEG + 1], Tm1[DEG + 1], Tc[DEG + 1], Tn[DEG + 1];
        for (int j = 0; j <= DEG; ++j) { mono[j] = 0; Tm1[j] = 0; Tc[j] = 0; }
        Tm1[0] = 1.0;            // T0
        Tc[1]  = 1.0;            // T1
        for (int j = 0; j <= DEG; ++j) mono[j] = c[0] * Tm1[j] + c[1] * Tc[j];
        for (int k = 2; k <= DEG; ++k) {
            for (int j = 0; j <= DEG; ++j) {
                double t = -Tm1[j];
                if (j > 0) t += 2.0 * Tc[j - 1];
                Tn[j] = t;
            }
            for (int j = 0; j <= DEG; ++j) {
                mono[j] += c[k] * Tn[j];
                Tm1[j] = Tc[j];
                Tc[j]  = Tn[j];
            }
        }
        for (int j = 0; j <= DEG; ++j) P.a[j] = (float)mono[j];
    }

    cudaFuncSetAttribute(logm_hmma_kernel,
                         cudaFuncAttributeMaxDynamicSharedMemorySize, SMEM_TOT);
    logm_hmma_kernel<<<nmat, 128, SMEM_TOT>>>(in, out, P);
}